// round 1
// baseline (speedup 1.0000x reference)
#include <cuda_runtime.h>

// Problem constants
#define B_   8
#define OBJ_ 128
#define INP_ 64
#define HID_ 256
#define D_   192          // 3*INP
#define ROWS_ (B_*OBJ_)   // 1024

// Scratch (allocation-free rule: __device__ globals)
__device__ float g_ea[ROWS_ * HID_];
__device__ float g_eb[ROWS_ * HID_];
__device__ float g_pooled[ROWS_ * HID_];

// ---------------------------------------------------------------------------
// Encoder: ea[row,h] = sum_d x[row,d] * w_enc[d,h];  eb uses w_enc[D+d,h]
// x = concat(x0,x1,x2) along last dim (64 each)
// ---------------------------------------------------------------------------
__global__ void enc_kernel(const float* __restrict__ x0,
                           const float* __restrict__ x1,
                           const float* __restrict__ x2,
                           const float* __restrict__ w_enc) {
    __shared__ float xs[D_];
    const int row = blockIdx.x;        // b*OBJ + n
    const int tid = threadIdx.x;       // 0..255
    if (tid < D_) {
        int part = tid >> 6;           // /64
        int d    = tid & 63;
        const float* src = (part == 0) ? x0 : ((part == 1) ? x1 : x2);
        xs[tid] = src[row * INP_ + d];
    }
    __syncthreads();
    float s1 = 0.f, s2 = 0.f;
    #pragma unroll 8
    for (int d = 0; d < D_; d++) {
        float xv = xs[d];
        s1 = fmaf(xv, w_enc[d * HID_ + tid], s1);
        s2 = fmaf(xv, w_enc[(D_ + d) * HID_ + tid], s2);
    }
    g_ea[row * HID_ + tid] = s1;
    g_eb[row * HID_ + tid] = s2;
}

// ---------------------------------------------------------------------------
// Main pairwise MLP + mean pooling.
// One CTA per (b,i). j in 2 chunks of 64. 3 layers of 256x256 GEMM in smem.
// Block = (32,8) = 256 threads. Thread tile = 8 rows x 8 cols.
// ---------------------------------------------------------------------------
#define JC 64
#define KC 32
// smem floats: 2*JC*HID (bufs) + KC*HID (W panel) + HID (ea) + HID (pooled)
#define SMEM_FLOATS (2*JC*HID_ + KC*HID_ + HID_ + HID_)
#define SMEM_BYTES  (SMEM_FLOATS * 4)

__global__ void __launch_bounds__(256, 1)
main_kernel(const float* __restrict__ b_enc,
            const float* __restrict__ w1, const float* __restrict__ b1,
            const float* __restrict__ w2, const float* __restrict__ b2,
            const float* __restrict__ w3, const float* __restrict__ b3) {
    extern __shared__ float sm[];
    float* buf0   = sm;                    // JC*HID
    float* buf1   = buf0 + JC * HID_;      // JC*HID
    float* wb     = buf1 + JC * HID_;      // KC*HID
    float* ea_s   = wb + KC * HID_;        // HID
    float* pooled = ea_s + HID_;           // HID

    const int bi = blockIdx.x;             // b*OBJ + i
    const int b  = bi >> 7;
    const int tx = threadIdx.x;            // 0..31 (col groups of 8)
    const int ty = threadIdx.y;            // 0..7  (row groups of 8)
    const int tid = ty * 32 + tx;

    ea_s[tid]   = g_ea[bi * HID_ + tid];
    pooled[tid] = 0.f;
    __syncthreads();

    const float* Ws[3] = {w1, w2, w3};
    const float* Bs[3] = {b1, b2, b3};

    for (int chunk = 0; chunk < 2; chunk++) {
        const int j0 = chunk * JC;
        // ---- build H0 = relu(ea + eb_j + b_enc) into buf0 ----
        const float* ebp = g_eb + (b * OBJ_ + j0) * HID_;
        #pragma unroll 4
        for (int idx = tid; idx < JC * HID_; idx += 256) {
            int h = idx & (HID_ - 1);
            float v = ea_s[h] + ebp[idx] + b_enc[h];
            buf0[idx] = fmaxf(v, 0.f);
        }
        __syncthreads();

        float* bin  = buf0;
        float* bout = buf1;
        #pragma unroll
        for (int L = 0; L < 3; L++) {
            const float* W    = Ws[L];
            const float* bias = Bs[L];
            float acc[8][8];
            #pragma unroll
            for (int r = 0; r < 8; r++)
                #pragma unroll
                for (int c = 0; c < 8; c++) acc[r][c] = 0.f;

            for (int k0 = 0; k0 < HID_; k0 += KC) {
                // stage W[k0..k0+KC) x HID into wb (KC*HID floats)
                const float4* Wg  = reinterpret_cast<const float4*>(W + k0 * HID_);
                float4*       wb4 = reinterpret_cast<float4*>(wb);
                #pragma unroll
                for (int t = 0; t < (KC * HID_ / 4) / 256; t++)
                    wb4[tid + t * 256] = Wg[tid + t * 256];
                __syncthreads();

                #pragma unroll 8
                for (int k = 0; k < KC; k++) {
                    float a[8];
                    #pragma unroll
                    for (int r = 0; r < 8; r++)
                        a[r] = bin[(ty * 8 + r) * HID_ + k0 + k];
                    const float4* wrow =
                        reinterpret_cast<const float4*>(wb + k * HID_ + tx * 8);
                    float4 wv0 = wrow[0];
                    float4 wv1 = wrow[1];
                    float wv[8] = {wv0.x, wv0.y, wv0.z, wv0.w,
                                   wv1.x, wv1.y, wv1.z, wv1.w};
                    #pragma unroll
                    for (int r = 0; r < 8; r++)
                        #pragma unroll
                        for (int c = 0; c < 8; c++)
                            acc[r][c] = fmaf(a[r], wv[c], acc[r][c]);
                }
                __syncthreads();
            }

            if (L < 2) {
                #pragma unroll
                for (int r = 0; r < 8; r++) {
                    #pragma unroll
                    for (int c = 0; c < 8; c++) {
                        float v = acc[r][c] + bias[tx * 8 + c];
                        bout[(ty * 8 + r) * HID_ + tx * 8 + c] = fmaxf(v, 0.f);
                    }
                }
                __syncthreads();
                float* t = bin; bin = bout; bout = t;
            } else {
                // layer 3: no relu; reduce rows into pooled
                #pragma unroll
                for (int c = 0; c < 8; c++) {
                    float s = 0.f;
                    #pragma unroll
                    for (int r = 0; r < 8; r++) s += acc[r][c];
                    s += 8.f * bias[tx * 8 + c];   // 8 rows per thread carry bias
                    atomicAdd(&pooled[tx * 8 + c], s);
                }
                __syncthreads();
            }
        }
    }
    g_pooled[bi * HID_ + tid] = pooled[tid] * (1.f / 128.f);
}

// ---------------------------------------------------------------------------
// Decoder: out = relu(pooled @ wd1 + bd1) @ wd2 + bd2
// ---------------------------------------------------------------------------
__global__ void dec_kernel(const float* __restrict__ wd1,
                           const float* __restrict__ bd1,
                           const float* __restrict__ wd2,
                           const float* __restrict__ bd2,
                           float* __restrict__ out) {
    __shared__ float p[HID_];
    __shared__ float t[HID_];
    const int row = blockIdx.x;
    const int tid = threadIdx.x;
    p[tid] = g_pooled[row * HID_ + tid];
    __syncthreads();
    float s = 0.f;
    #pragma unroll 8
    for (int k = 0; k < HID_; k++)
        s = fmaf(p[k], wd1[k * HID_ + tid], s);
    t[tid] = fmaxf(s + bd1[tid], 0.f);
    __syncthreads();
    if (tid < INP_) {
        float s2 = 0.f;
        #pragma unroll 8
        for (int k = 0; k < HID_; k++)
            s2 = fmaf(t[k], wd2[k * INP_ + tid], s2);
        out[row * INP_ + tid] = s2 + bd2[tid];
    }
}

// ---------------------------------------------------------------------------
extern "C" void kernel_launch(void* const* d_in, const int* in_sizes, int n_in,
                              void* d_out, int out_size) {
    const float* x0    = (const float*)d_in[0];
    const float* x1    = (const float*)d_in[1];
    const float* x2    = (const float*)d_in[2];
    const float* w_enc = (const float*)d_in[3];
    const float* b_enc = (const float*)d_in[4];
    const float* w1    = (const float*)d_in[5];
    const float* b1    = (const float*)d_in[6];
    const float* w2    = (const float*)d_in[7];
    const float* b2    = (const float*)d_in[8];
    const float* w3    = (const float*)d_in[9];
    const float* b3    = (const float*)d_in[10];
    const float* wd1   = (const float*)d_in[11];
    const float* bd1   = (const float*)d_in[12];
    const float* wd2   = (const float*)d_in[13];
    const float* bd2   = (const float*)d_in[14];
    float* out = (float*)d_out;

    cudaFuncSetAttribute(main_kernel,
                         cudaFuncAttributeMaxDynamicSharedMemorySize, SMEM_BYTES);

    enc_kernel<<<ROWS_, 256>>>(x0, x1, x2, w_enc);
    main_kernel<<<ROWS_, dim3(32, 8), SMEM_BYTES>>>(b_enc, w1, b1, w2, b2, w3, b3);
    dec_kernel<<<ROWS_, 256>>>(wd1, bd1, wd2, bd2, out);
}